// round 16
// baseline (speedup 1.0000x reference)
#include <cuda_runtime.h>
#include <cuda_fp16.h>
#include <cstdint>

// ============================================================================
// out[8192,1536] = x[8192,3072] @ (mask.T * w)[3072,1536] + b
// R16: 512-k chunks, 2-stage double buffer (64KB x 2), CTA 512x64 with 512
//      threads (16 warps, warp tile 32x64), 1 CTA/SM. Halves barrier count
//      again AND halves per-SM B smem traffic (single B stream per SM).
// ============================================================================

static constexpr int MDIM = 8192;
static constexpr int NDIM = 1536;
static constexpr int KDIM = 3072;

static constexpr int TM = 512;
static constexpr int TN = 64;
static constexpr int TKC = 512;             // halves per pipeline chunk
static constexpr int TILES_N = NDIM / TN;   // 24
static constexpr int TILES_M = MDIM / TM;   // 16
static constexpr int KB16 = KDIM / 16;      // 192 16-k fragment blocks

static constexpr int SUB_BYTES = TN * 64 * 2;       // 8192 (one 64-k sub-tile)
static constexpr int STAGE_BYTES = 8 * SUB_BYTES;   // 65536
static constexpr int SMEM_TOTAL = 2 * STAGE_BYTES;  // 131072 -> 1 CTA/SM

// Prep kernel grid split
static constexpr int CONV_BLOCKS = (MDIM / 16) * KB16 / 8;        // 12288
static constexpr int PREPB_BLOCKS = (KDIM / 32) * (NDIM / 32);    // 4608

// A in fragment-major layout: frag (mb, kb) -> 32 lanes x 16B
__device__ uint4  g_xfrag[(size_t)(MDIM / 16) * KB16 * 32];
__device__ __half g_Bh[(size_t)NDIM * KDIM];   // 9.4 MB, [n][k]

// ---------------------------------------------------------------------------
// PTX helpers
// ---------------------------------------------------------------------------
__device__ __forceinline__ uint32_t smem_u32(const void* p) {
    uint32_t a;
    asm("{ .reg .u64 t; cvta.to.shared.u64 t, %1; cvt.u32.u64 %0, t; }" : "=r"(a) : "l"(p));
    return a;
}

#define CP_ASYNC16(dst, src) \
    asm volatile("cp.async.cg.shared.global [%0], [%1], 16;" :: "r"(dst), "l"(src) : "memory")
#define CP_COMMIT() asm volatile("cp.async.commit_group;" ::: "memory")
#define CP_WAIT0()  asm volatile("cp.async.wait_group 0;" ::: "memory")

#define LDSM_X4(r0, r1, r2, r3, addr) \
    asm volatile("ldmatrix.sync.aligned.m8n8.x4.shared.b16 {%0,%1,%2,%3}, [%4];" \
                 : "=r"(r0), "=r"(r1), "=r"(r2), "=r"(r3) : "r"(addr))

#define MMA16816(d, a0, a1, a2, a3, b0, b1) \
    asm volatile("mma.sync.aligned.m16n8k16.row.col.f32.f16.f16.f32 " \
                 "{%0,%1,%2,%3}, {%4,%5,%6,%7}, {%8,%9}, {%0,%1,%2,%3};" \
                 : "+f"((d)[0]), "+f"((d)[1]), "+f"((d)[2]), "+f"((d)[3]) \
                 : "r"(a0), "r"(a1), "r"(a2), "r"(a3), "r"(b0), "r"(b1))

// ---------------------------------------------------------------------------
// Fused prep kernel (unchanged from R15)
// ---------------------------------------------------------------------------
__global__ void __launch_bounds__(256) prep_kernel(const float* __restrict__ x,
                                                   const float* __restrict__ w,
                                                   const float* __restrict__ mask) {
    if (blockIdx.x < CONV_BLOCKS) {
        int f = blockIdx.x * 8 + (threadIdx.x >> 5);   // fragment id
        int lane = threadIdx.x & 31;
        int mb = f / KB16;
        int kb = f - mb * KB16;
        int r = mb * 16 + (lane >> 2);
        int c = kb * 16 + (lane & 3) * 2;
        const float* p00 = x + (size_t)r * KDIM + c;
        float2 v00 = *reinterpret_cast<const float2*>(p00);
        float2 v10 = *reinterpret_cast<const float2*>(p00 + 8 * KDIM);
        float2 v01 = *reinterpret_cast<const float2*>(p00 + 8);
        float2 v11 = *reinterpret_cast<const float2*>(p00 + 8 * KDIM + 8);
        __half2 h0 = __floats2half2_rn(v00.x, v00.y);
        __half2 h1 = __floats2half2_rn(v10.x, v10.y);
        __half2 h2 = __floats2half2_rn(v01.x, v01.y);
        __half2 h3 = __floats2half2_rn(v11.x, v11.y);
        uint4 u;
        u.x = *reinterpret_cast<uint32_t*>(&h0);
        u.y = *reinterpret_cast<uint32_t*>(&h1);
        u.z = *reinterpret_cast<uint32_t*>(&h2);
        u.w = *reinterpret_cast<uint32_t*>(&h3);
        g_xfrag[(size_t)f * 32 + lane] = u;
    } else {
        __shared__ float ws[32][33];
        int bb = blockIdx.x - CONV_BLOCKS;
        int k0 = (bb % (KDIM / 32)) * 32;
        int n0 = (bb / (KDIM / 32)) * 32;
        int tx = threadIdx.x & 31;
        int ty = threadIdx.x >> 5;
#pragma unroll
        for (int i = 0; i < 32; i += 8)
            ws[ty + i][tx] = w[(size_t)(k0 + ty + i) * NDIM + (n0 + tx)];
        __syncthreads();
#pragma unroll
        for (int i = 0; i < 32; i += 8) {
            int n = n0 + ty + i;
            int k = k0 + tx;
            size_t idx = (size_t)n * KDIM + k;
            g_Bh[idx] = __float2half(mask[idx] * ws[tx][ty + i]);
        }
    }
}

// ---------------------------------------------------------------------------
// GEMM. CTA 512x64, 16 warps each 32(M)x64(N). A via LDG.128 of pre-packed
// fragments; B via 2-stage cp.async (512-k chunks) + per-ks double-buffered
// LDSM. Structural-zero chunks skipped; LPT order.
// ---------------------------------------------------------------------------
__global__ void __launch_bounds__(512, 1) gemm_f16_kernel(const float* __restrict__ bias,
                                                          float* __restrict__ out) {
    extern __shared__ char smem[];
    const uint32_t sbase = smem_u32(smem);
    const int tid = threadIdx.x;
    const int wid = tid >> 5;      // 0..15 -> rows wid*32 .. +31
    const int lane = tid & 31;

    // LPT tile mapping: long tiles (ub1: tn in [8,16)) first. 384 CTAs total.
    int tm, tn;
    if (blockIdx.x < 128) {
        tm = blockIdx.x >> 3;                 // 0..15
        tn = 8 + (blockIdx.x & 7);            // 8..15 (ub1)
    } else {
        int idx = blockIdx.x - 128;
        tm = idx >> 4;                        // 0..15
        int r = idx & 15;
        tn = (r < 8) ? r : (8 + r);           // 0..7 or 16..23
    }
    const int m0 = tm * TM;
    const int n0 = tn * TN;

    // Structural-zero skipping over 512-wide k-chunks.
    //   ub0: chunks {0,1,3,4} -> 4 iters, kc = i + (i>=2)
    //   ub1: chunks {0..5}    -> 6 iters, kc = i
    //   ub2: chunks {1,2,4,5} -> 4 iters, kc = i + 1 + (i>=2)
    const int ub = n0 >> 9;
    const int niter  = (ub == 1) ? 6 : 4;
    const int kbase  = (ub == 2) ? 1 : 0;
    const int thresh = (ub == 1) ? 6 : 2;
#define KCHUNK(i) ((i) + kbase + (((i) >= thresh) ? 1 : 0))

    float acc[2][8][4];
#pragma unroll
    for (int i = 0; i < 2; ++i)
#pragma unroll
        for (int j = 0; j < 8; ++j)
#pragma unroll
            for (int q = 0; q < 4; ++q) acc[i][j][q] = 0.0f;

    // B chunk loader: 8 sub-tiles x (64 rows x 128 B); 4096 16B chunks,
    // 512 threads -> 8 per thread (1 per sub-tile).
    const __half* bbase_g = g_Bh + (size_t)n0 * KDIM;
    auto load_B = [&](int s, int kc) {
        uint32_t sa = sbase + s * STAGE_BYTES;
#pragma unroll
        for (int sub = 0; sub < 8; ++sub) {
            const __half* ba = bbase_g + kc * TKC + sub * 64;
            uint32_t dsub = sa + sub * SUB_BYTES;
            int row = tid >> 3, q = tid & 7;
            uint32_t dst = dsub + row * 128 + ((q ^ (row & 7)) << 4);
            CP_ASYNC16(dst, ba + (size_t)row * KDIM + q * 8);
        }
    };

    // Prologue: load chunk 0 into stage 0
    load_B(0, KCHUNK(0));
    CP_COMMIT();

    // A fragment bases
    const uint4* afrag0 = g_xfrag + ((size_t)(m0 / 16 + wid * 2 + 0) * KB16) * 32 + lane;
    const uint4* afrag1 = g_xfrag + ((size_t)(m0 / 16 + wid * 2 + 1) * KB16) * 32 + lane;

    // B ldmatrix per-lane selectors
    const int b_rowsel = ((lane >> 4) << 3) + (lane & 7);  // + g*16
    const int b_chunksel = (lane >> 3) & 1;                // + (ks&3)*2

    uint4 af[2][4];         // [pair buf][ks_in_pair*2 + mt]
    uint32_t bf[2][4][4];   // [ks buf][g][frag]

    auto load_bf = [&](int buf, uint32_t bBase, int ks) {
        const uint32_t subBase = bBase + (ks >> 2) * SUB_BYTES;
        const int chunk = (ks & 3) * 2 + b_chunksel;
#pragma unroll
        for (int g = 0; g < 4; ++g) {
            int row = g * 16 + b_rowsel;
            uint32_t addr = subBase + row * 128 + ((chunk ^ (row & 7)) << 4);
            LDSM_X4(bf[buf][g][0], bf[buf][g][1], bf[buf][g][2], bf[buf][g][3], addr);
        }
    };

    int stage = 0;
    for (int j = 0; j < niter; ++j) {
        const int kb0 = KCHUNK(j) * 32;  // first 16-k fragment block of chunk
        // A: prefetch pair 0 (ks 0,1) before the wait to cover L2 latency
        af[0][0] = afrag0[(size_t)(kb0 + 0) * 32];
        af[0][1] = afrag1[(size_t)(kb0 + 0) * 32];
        af[0][2] = afrag0[(size_t)(kb0 + 1) * 32];
        af[0][3] = afrag1[(size_t)(kb0 + 1) * 32];

        CP_WAIT0();          // chunk j's data fully landed (this thread's part)
        __syncthreads();     // publishes chunk j; proves all warps done with j-1

        if (j + 1 < niter) {
            load_B(stage ^ 1, KCHUNK(j + 1));   // overlaps with compute of j
            CP_COMMIT();
        }

        const uint32_t bBase = sbase + stage * STAGE_BYTES;
        stage ^= 1;

        // B: prefetch ks=0 into buffer 0 (single refill point per chunk)
        load_bf(0, bBase, 0);

#pragma unroll
        for (int ks = 0; ks < 32; ++ks) {
            const int cb = ks & 1;          // current B buffer
            const int ap = (ks >> 1) & 1;   // current A pair buffer
            if ((ks & 1) == 0 && ks < 30) {
                const int kn = kb0 + ks + 2;
                af[ap ^ 1][0] = afrag0[(size_t)(kn + 0) * 32];
                af[ap ^ 1][1] = afrag1[(size_t)(kn + 0) * 32];
                af[ap ^ 1][2] = afrag0[(size_t)(kn + 1) * 32];
                af[ap ^ 1][3] = afrag1[(size_t)(kn + 1) * 32];
            }
            if (ks < 31) load_bf(cb ^ 1, bBase, ks + 1);

            const int ai = (ks & 1) * 2;
#pragma unroll
            for (int mt = 0; mt < 2; ++mt)
#pragma unroll
                for (int nt = 0; nt < 8; ++nt) {
                    const uint32_t b0 = bf[cb][nt >> 1][(nt & 1) * 2 + 0];
                    const uint32_t b1 = bf[cb][nt >> 1][(nt & 1) * 2 + 1];
                    MMA16816(acc[mt][nt], af[ap][ai + mt].x, af[ap][ai + mt].y,
                             af[ap][ai + mt].z, af[ap][ai + mt].w, b0, b1);
                }
        }
    }
#undef KCHUNK

    // Epilogue
    const int grp = lane >> 2, tig = lane & 3;
#pragma unroll
    for (int mt = 0; mt < 2; ++mt) {
        const int row0 = m0 + wid * 32 + mt * 16 + grp;
#pragma unroll
        for (int nt = 0; nt < 8; ++nt) {
            const int col = n0 + nt * 8 + tig * 2;
            const float2 bb = *reinterpret_cast<const float2*>(bias + col);
            float2 v0, v1;
            v0.x = acc[mt][nt][0] + bb.x;
            v0.y = acc[mt][nt][1] + bb.y;
            v1.x = acc[mt][nt][2] + bb.x;
            v1.y = acc[mt][nt][3] + bb.y;
            *reinterpret_cast<float2*>(out + (size_t)row0 * NDIM + col) = v0;
            *reinterpret_cast<float2*>(out + (size_t)(row0 + 8) * NDIM + col) = v1;
        }
    }
}

// ---------------------------------------------------------------------------
// Launch
// ---------------------------------------------------------------------------
extern "C" void kernel_launch(void* const* d_in, const int* in_sizes, int n_in,
                              void* d_out, int out_size) {
    const float* x    = (const float*)d_in[0];   // [8192, 3072]
    const float* w    = (const float*)d_in[1];   // [3072, 1536]
    const float* b    = (const float*)d_in[2];   // [1536]
    const float* mask = (const float*)d_in[3];   // [1536, 3072]
    float* out = (float*)d_out;                  // [8192, 1536]

    // 1) Fused prep
    prep_kernel<<<CONV_BLOCKS + PREPB_BLOCKS, 256>>>(x, w, mask);

    // 2) GEMM
    cudaFuncSetAttribute(gemm_f16_kernel, cudaFuncAttributeMaxDynamicSharedMemorySize,
                         SMEM_TOTAL);
    gemm_f16_kernel<<<TILES_M * TILES_N, 512, SMEM_TOTAL>>>(b, out);
}